// round 13
// baseline (speedup 1.0000x reference)
#include <cuda_runtime.h>
#include <cuda_fp16.h>
#include <cstdint>

// Problem constants (fixed by the dataset)
#define NN_NODES 10000
#define NN_EDGES 120000
#define IN_W 6
#define WN 32
#define WK 256
#define DEPTH 4

// ---------------- scratch (device globals; no allocation allowed) ----------
__device__ __half g_we [(size_t)NN_EDGES * WN * WN];   // per-edge weight mats (fp16)
__device__ __half g_h1 [(size_t)NN_EDGES * (WK / 2)];  // edge MLP hidden 1 (fp16)
__device__ __half g_h2 [(size_t)NN_EDGES * WK];        // edge MLP hidden 2 (fp16)
__device__ __half g_k2 [(WK / 2) * WK];                // k2 fp16
__device__ __half g_k3 [WK * WN * WN];                 // k3 fp16
__device__ float g_h   [(size_t)NN_NODES * WN];
__device__ float g_aggr[(size_t)NN_NODES * WN];
__device__ float g_deg [NN_NODES];

// ---------------- shared PTX helpers ----------------------------------------
__device__ __forceinline__ void cp16(uint32_t dst, const void* src, int sbytes) {
    asm volatile("cp.async.cg.shared.global [%0], [%1], 16, %2;\n"
                 :: "r"(dst), "l"(src), "r"(sbytes));
}
__device__ __forceinline__ void ldsm_x4(uint32_t* r, uint32_t addr) {
    asm volatile("ldmatrix.sync.aligned.m8n8.x4.shared.b16 {%0,%1,%2,%3}, [%4];"
                 : "=r"(r[0]), "=r"(r[1]), "=r"(r[2]), "=r"(r[3]) : "r"(addr));
}
__device__ __forceinline__ void ldsm_x4t(uint32_t* r, uint32_t addr) {
    asm volatile("ldmatrix.sync.aligned.m8n8.x4.trans.shared.b16 {%0,%1,%2,%3}, [%4];"
                 : "=r"(r[0]), "=r"(r[1]), "=r"(r[2]), "=r"(r[3]) : "r"(addr));
}
__device__ __forceinline__ void mma16816(float* c, const uint32_t* a, uint32_t b0, uint32_t b1) {
    asm volatile("mma.sync.aligned.m16n8k16.row.col.f32.f16.f16.f32 "
                 "{%0,%1,%2,%3}, {%4,%5,%6,%7}, {%8,%9}, {%0,%1,%2,%3};"
                 : "+f"(c[0]), "+f"(c[1]), "+f"(c[2]), "+f"(c[3])
                 : "r"(a[0]), "r"(a[1]), "r"(a[2]), "r"(a[3]), "r"(b0), "r"(b1));
}

// ============================================================================
// Unified pure-fp16 GEMM: C = act(A@B + bias), fp16 out.
// Tile 256x128, BK=64, 8 warps (warp tile 64x64, 4m x 2n), 3-stage ring.
// Per-stage smem: A 256x144B (36864) + B 64x272B (17408) = 54272; x3 = 162816.
// 1 CTA/SM (regs ~190); A warp-amplification 2x, B 4x -> 128KB LDSM/tile.
// ============================================================================
#define A_PITCH 144                     // 64 halves + 8 pad
#define AT_BYTES (256 * A_PITCH)        // 36864
#define BT_BYTES (64 * 272)             // 17408
#define STAGE_B (AT_BYTES + BT_BYTES)   // 54272
#define GEMM_SMEM (3 * STAGE_B)         // 162816

__global__ __launch_bounds__(256, 1)
void gemm_fp16_256(const __half* __restrict__ Ah, const __half* __restrict__ Bh,
                   const float* __restrict__ bias, __half* __restrict__ Cout,
                   int M, int N, int K, int doRelu)
{
    extern __shared__ __half smem[];
    const int tid  = threadIdx.x;
    const int lane = tid & 31;
    const int wid  = tid >> 5;
    const int bm = blockIdx.y * 256;
    const int bn = blockIdx.x * 128;
    const int warp_m = (wid & 3) * 64;
    const int warp_n = (wid >> 2) * 64;

    uint32_t su = (uint32_t)__cvta_generic_to_shared(smem);

    float C[4][8][4];
#pragma unroll
    for (int mt = 0; mt < 4; mt++)
#pragma unroll
        for (int nt = 0; nt < 8; nt++)
#pragma unroll
            for (int q = 0; q < 4; q++) C[mt][nt][q] = 0.f;

    const int nk = K / 64;

    auto load_tile = [&](int kt, int st) {
        const int k0 = kt * 64;
        const uint32_t base = su + (uint32_t)st * STAGE_B;
        // A: 256 rows x 8 chunks (16B) = 2048 chunks
#pragma unroll
        for (int t = 0; t < 8; t++) {
            int cid = tid + t * 256;
            int rr  = cid >> 3;
            int cc  = cid & 7;
            int gr  = bm + rr;
            int ok  = (gr < M) ? 16 : 0;
            const __half* src = Ah + (size_t)(ok ? gr : 0) * K + k0 + cc * 8;
            cp16(base + (uint32_t)(rr * A_PITCH + cc * 16), src, ok);
        }
        // B: 64 rows x 16 chunks = 1024 chunks
#pragma unroll
        for (int t = 0; t < 4; t++) {
            int cid = tid + t * 256;
            int rr  = cid >> 4;
            int cc  = cid & 15;
            const __half* src = Bh + (size_t)(k0 + rr) * N + bn + cc * 8;
            cp16(base + AT_BYTES + (uint32_t)(rr * 272 + cc * 16), src, 16);
        }
    };

    load_tile(0, 0);
    asm volatile("cp.async.commit_group;\n" ::: "memory");
    if (nk > 1) load_tile(1, 1);
    asm volatile("cp.async.commit_group;\n" ::: "memory");

    for (int i = 0; i < nk; i++) {
        const int st = i % 3;
        asm volatile("cp.async.wait_group 1;\n" ::: "memory");
        __syncthreads();
        if (i + 2 < nk) load_tile(i + 2, (i + 2) % 3);
        asm volatile("cp.async.commit_group;\n" ::: "memory");

        const uint32_t aS = su + (uint32_t)st * STAGE_B;
        const uint32_t bS = aS + AT_BYTES;

        const int arow = lane & 15;
        const int acol = (lane >> 4) * 8;
        const int bk  = ((lane >> 3) & 1) * 8 + (lane & 7);
        const int bn8 = (lane >> 4) * 8;

#pragma unroll
        for (int ks = 0; ks < 64; ks += 16) {
            uint32_t bh[4][4];
#pragma unroll
            for (int ntp = 0; ntp < 4; ntp++) {
                uint32_t boff = (uint32_t)((ks + bk) * 272 + (warp_n + ntp * 16 + bn8) * 2);
                ldsm_x4t(bh[ntp], bS + boff);
            }
            uint32_t ah[4][4];
#pragma unroll
            for (int mt = 0; mt < 4; mt++) {
                uint32_t off = (uint32_t)((warp_m + mt * 16 + arow) * A_PITCH + (ks + acol) * 2);
                ldsm_x4(ah[mt], aS + off);
            }
#pragma unroll
            for (int mt = 0; mt < 4; mt++)
#pragma unroll
                for (int nt = 0; nt < 8; nt++)
                    mma16816(C[mt][nt], ah[mt],
                             bh[nt >> 1][(nt & 1) * 2], bh[nt >> 1][(nt & 1) * 2 + 1]);
        }
    }

    __syncthreads();

#pragma unroll
    for (int mt = 0; mt < 4; mt++) {
#pragma unroll
        for (int nt = 0; nt < 8; nt++) {
            int r0  = bm + warp_m + mt * 16 + (lane >> 2);
            int col = bn + warp_n + nt * 8 + (lane & 3) * 2;
            float b0 = bias[col], b1 = bias[col + 1];
            float v0 = C[mt][nt][0] + b0;
            float v1 = C[mt][nt][1] + b1;
            float v2 = C[mt][nt][2] + b0;
            float v3 = C[mt][nt][3] + b1;
            if (doRelu) {
                v0 = fmaxf(v0, 0.f); v1 = fmaxf(v1, 0.f);
                v2 = fmaxf(v2, 0.f); v3 = fmaxf(v3, 0.f);
            }
            if (r0 < M) {
                __half2 p; p.x = __float2half(v0); p.y = __float2half(v1);
                *reinterpret_cast<__half2*>(&Cout[(size_t)r0 * N + col]) = p;
            }
            if (r0 + 8 < M) {
                __half2 p; p.x = __float2half(v2); p.y = __float2half(v3);
                *reinterpret_cast<__half2*>(&Cout[(size_t)(r0 + 8) * N + col]) = p;
            }
        }
    }
}

// ---------------- small kernels --------------------------------------------

// single launch converting both k2 and k3 fp32 -> fp16 (grid-stride)
__global__ void convert_both_kernel(const float* __restrict__ k2_w, const float* __restrict__ k3_w)
{
    const int n2 = (WK / 2) * WK;
    const int n3 = WK * WN * WN;
    for (int i = blockIdx.x * blockDim.x + threadIdx.x; i < n2 + n3; i += gridDim.x * blockDim.x) {
        if (i < n2) g_k2[i] = __float2half(k2_w[i]);
        else        g_k3[i - n2] = __float2half(k3_w[i - n2]);
    }
}

// h1 = relu(ea @ k1_w + k1_b), fp16. 256 threads = 2 edges per block.
__global__ __launch_bounds__(256)
void edge_fc1_kernel(const float* __restrict__ ea, const float* __restrict__ w,
                     const float* __restrict__ b, int E)
{
    int sub = threadIdx.x >> 7;
    int tid = threadIdx.x & 127;
    int e = blockIdx.x * 2 + sub;
    if (e >= E) return;
    __shared__ float a[2][IN_W];
    if (tid < IN_W) a[sub][tid] = ea[(size_t)e * IN_W + tid];
    __syncthreads();
    float acc = b[tid];
#pragma unroll
    for (int i = 0; i < IN_W; i++) acc = fmaf(a[sub][i], w[i * (WK / 2) + tid], acc);
    acc = fmaxf(acc, 0.f);
    g_h1[(size_t)e * (WK / 2) + tid] = __float2half(acc);
}

__global__ void deg_kernel(const int* __restrict__ dst, int E)
{
    int e = blockIdx.x * blockDim.x + threadIdx.x;
    if (e < E) atomicAdd(&g_deg[dst[e]], 1.f);
}

__global__ __launch_bounds__(256)
void fc1_kernel(const float* __restrict__ x, const float* __restrict__ w,
                const float* __restrict__ b, int N)
{
    int warp = threadIdx.x >> 5, lane = threadIdx.x & 31;
    int n = blockIdx.x * 8 + warp;
    if (n >= N) return;
    float xv = (lane < IN_W) ? x[(size_t)n * IN_W + lane] : 0.f;
    float acc = b[lane];
#pragma unroll
    for (int i = 0; i < IN_W; i++) {
        float xi = __shfl_sync(0xffffffffu, xv, i);
        acc = fmaf(xi, w[i * WN + lane], acc);
    }
    g_h[(size_t)n * WN + lane] = acc;
}

// per-edge matvec msg = h[src] @ w_e (fp16), scattered to aggr[dst].
__global__ __launch_bounds__(256)
void msg_scatter_kernel(const int* __restrict__ src, const int* __restrict__ dst, int E)
{
    int warp = threadIdx.x >> 5, lane = threadIdx.x & 31;
    int e = blockIdx.x * 8 + warp;
    if (e >= E) return;
    int s = src[e], d = dst[e];
    float hv = g_h[(size_t)s * WN + lane];
    const uint4* w4 = reinterpret_cast<const uint4*>(&g_we[(size_t)e * WN * WN]);
    uint4 q0 = w4[lane];
    uint4 q1 = w4[lane + 32];
    uint4 q2 = w4[lane + 64];
    uint4 q3 = w4[lane + 96];
    const int rbase = lane >> 2;
    float acc[8];
#pragma unroll
    for (int j = 0; j < 8; j++) acc[j] = 0.f;

    auto accum = [&](const uint4& q, int k) {
        float hk = __shfl_sync(0xffffffffu, hv, rbase + 8 * k);
        const __half2* hp = reinterpret_cast<const __half2*>(&q);
#pragma unroll
        for (int p = 0; p < 4; p++) {
            float2 wf = __half22float2(hp[p]);
            acc[2 * p]     = fmaf(hk, wf.x, acc[2 * p]);
            acc[2 * p + 1] = fmaf(hk, wf.y, acc[2 * p + 1]);
        }
    };
    accum(q0, 0); accum(q1, 1); accum(q2, 2); accum(q3, 3);

#pragma unroll
    for (int m = 4; m <= 16; m <<= 1)
#pragma unroll
        for (int j = 0; j < 8; j++)
            acc[j] += __shfl_xor_sync(0xffffffffu, acc[j], m);

    if (rbase < 4) {
        float* p = &g_aggr[(size_t)d * WN + 8 * (lane & 3) + 2 * rbase];
        asm volatile("red.global.add.v2.f32 [%0], {%1, %2};"
                     :: "l"(p), "f"(acc[2 * rbase]), "f"(acc[2 * rbase + 1]) : "memory");
    }
}

// h = [relu]( aggr/denom + h @ root_w + conv_b ); also zeroes aggr for next round
__global__ __launch_bounds__(256)
void combine_kernel(const float* __restrict__ root_w, const float* __restrict__ conv_b,
                    int N, int doRelu)
{
    __shared__ float rw[WN * WN];
    __shared__ float cb[WN];
    int tid = threadIdx.x;
    for (int i = tid; i < WN * WN; i += blockDim.x) rw[i] = root_w[i];
    if (tid < WN) cb[tid] = conv_b[tid];
    __syncthreads();

    int warp = tid >> 5, lane = tid & 31;
    int n = blockIdx.x * 8 + warp;
    if (n >= N) return;
    float hv = g_h[(size_t)n * WN + lane];
    float denom = fmaxf(g_deg[n], 1.f);
    float acc = g_aggr[(size_t)n * WN + lane] / denom + cb[lane];
    g_aggr[(size_t)n * WN + lane] = 0.f;
#pragma unroll
    for (int i = 0; i < WN; i++) {
        float hi = __shfl_sync(0xffffffffu, hv, i);
        acc = fmaf(hi, rw[i * WN + lane], acc);
    }
    if (doRelu) acc = fmaxf(acc, 0.f);
    g_h[(size_t)n * WN + lane] = acc;
}

__global__ __launch_bounds__(128)
void head_kernel(const float* __restrict__ fc2_w, const float* __restrict__ fc2_b,
                 const float* __restrict__ fc3_w, const float* __restrict__ fc3_b,
                 float* __restrict__ out)
{
    int n = blockIdx.x, tid = threadIdx.x;
    __shared__ float sh[WN];
    __shared__ float red[4];
    if (tid < WN) sh[tid] = g_h[(size_t)n * WN + tid];
    __syncthreads();
    float a = fc2_b[tid];
#pragma unroll
    for (int i = 0; i < WN; i++) a = fmaf(sh[i], fc2_w[i * 128 + tid], a);
    a = fmaxf(a, 0.f) * fc3_w[tid];
#pragma unroll
    for (int o = 16; o; o >>= 1) a += __shfl_xor_sync(0xffffffffu, a, o);
    if ((tid & 31) == 0) red[tid >> 5] = a;
    __syncthreads();
    if (tid == 0) out[n] = red[0] + red[1] + red[2] + red[3] + fc3_b[0];
}

// ---------------- launch ----------------------------------------------------
extern "C" void kernel_launch(void* const* d_in, const int* in_sizes, int n_in,
                              void* d_out, int out_size)
{
    const float* x      = (const float*)d_in[0];
    const int*   ei     = (const int*)  d_in[1];
    const float* ea     = (const float*)d_in[2];
    const float* fc1_w  = (const float*)d_in[3];
    const float* fc1_b  = (const float*)d_in[4];
    const float* k1_w   = (const float*)d_in[5];
    const float* k1_b   = (const float*)d_in[6];
    const float* k2_w   = (const float*)d_in[7];
    const float* k2_b   = (const float*)d_in[8];
    const float* k3_w   = (const float*)d_in[9];
    const float* k3_b   = (const float*)d_in[10];
    const float* root_w = (const float*)d_in[11];
    const float* conv_b = (const float*)d_in[12];
    const float* fc2_w  = (const float*)d_in[13];
    const float* fc2_b  = (const float*)d_in[14];
    const float* fc3_w  = (const float*)d_in[15];
    const float* fc3_b  = (const float*)d_in[16];
    float* out = (float*)d_out;

    const int N = in_sizes[0] / IN_W;
    const int E = in_sizes[1] / 2;
    const int* src = ei;
    const int* dst = ei + E;

    float *aggr, *deg;
    __half *we, *h1, *h2, *k2, *k3;
    cudaGetSymbolAddress((void**)&we,   g_we);
    cudaGetSymbolAddress((void**)&aggr, g_aggr);
    cudaGetSymbolAddress((void**)&deg,  g_deg);
    cudaGetSymbolAddress((void**)&h1,   g_h1);
    cudaGetSymbolAddress((void**)&h2,   g_h2);
    cudaGetSymbolAddress((void**)&k2,   g_k2);
    cudaGetSymbolAddress((void**)&k3,   g_k3);

    static bool attr_done = false;
    if (!attr_done) {
        cudaFuncSetAttribute(gemm_fp16_256, cudaFuncAttributeMaxDynamicSharedMemorySize, GEMM_SMEM);
        attr_done = true;
    }

    // launch order: GEMM3 at my index 3 (observed ncu -s 5 window)
    edge_fc1_kernel<<<(E + 1) / 2, 256>>>(ea, k1_w, k1_b, E);                              // 0
    convert_both_kernel<<<256, 256>>>(k2_w, k3_w);                                         // 1
    // GEMM2 (pure fp16): h2 = relu(h1 @ k2 + b2).  M=E, N=256, K=128
    {
        dim3 grid(WK / 128, (E + 255) / 256);
        gemm_fp16_256<<<grid, 256, GEMM_SMEM>>>(h1, k2, k2_b, h2, E, WK, WK / 2, 1);       // 2
    }
    // GEMM3 (pure fp16): w_e = h2 @ k3 + b3.  M=E, N=1024, K=256
    {
        dim3 grid(WN * WN / 128, (E + 255) / 256);
        gemm_fp16_256<<<grid, 256, GEMM_SMEM>>>(h2, k3, k3_b, we, E, WN * WN, WK, 0);      // 3
    }
    fc1_kernel<<<(N + 7) / 8, 256>>>(x, fc1_w, fc1_b, N);                                  // 4

    // in-degree + one-time aggr clear
    cudaMemsetAsync(deg, 0, (size_t)N * sizeof(float));
    cudaMemsetAsync(aggr, 0, (size_t)N * WN * sizeof(float));
    deg_kernel<<<(E + 255) / 256, 256>>>(dst, E);

    // message passing (combine zeroes aggr for the next depth)
    for (int d = 0; d < DEPTH; d++) {
        msg_scatter_kernel<<<(E + 7) / 8, 256>>>(src, dst, E);
        combine_kernel<<<(N + 7) / 8, 256>>>(root_w, conv_b, N, d != DEPTH - 1 ? 1 : 0);
    }

    // head
    head_kernel<<<N, 128>>>(fc2_w, fc2_b, fc3_w, fc3_b, out);
}

// round 14
// speedup vs baseline: 1.0817x; 1.0817x over previous
#include <cuda_runtime.h>
#include <cuda_fp16.h>
#include <cstdint>

// Problem constants (fixed by the dataset)
#define NN_NODES 10000
#define NN_EDGES 120000
#define IN_W 6
#define WN 32
#define WK 256
#define DEPTH 4

// ---------------- scratch (device globals; no allocation allowed) ----------
__device__ __half g_we [(size_t)NN_EDGES * WN * WN];   // per-edge weight mats (fp16)
__device__ __half g_h1 [(size_t)NN_EDGES * (WK / 2)];  // edge MLP hidden 1 (fp16)
__device__ __half g_h2 [(size_t)NN_EDGES * WK];        // edge MLP hidden 2 (fp16)
__device__ __half g_k2 [(WK / 2) * WK];                // k2 fp16
__device__ __half g_k3 [WK * WN * WN];                 // k3 fp16
__device__ float g_h   [(size_t)NN_NODES * WN];
__device__ float g_aggr[(size_t)NN_NODES * WN];
__device__ float g_deg [NN_NODES];

// ---------------- shared PTX helpers ----------------------------------------
__device__ __forceinline__ void cp16(uint32_t dst, const void* src, int sbytes) {
    asm volatile("cp.async.cg.shared.global [%0], [%1], 16, %2;\n"
                 :: "r"(dst), "l"(src), "r"(sbytes));
}
__device__ __forceinline__ void ldsm_x4(uint32_t* r, uint32_t addr) {
    asm volatile("ldmatrix.sync.aligned.m8n8.x4.shared.b16 {%0,%1,%2,%3}, [%4];"
                 : "=r"(r[0]), "=r"(r[1]), "=r"(r[2]), "=r"(r[3]) : "r"(addr));
}
__device__ __forceinline__ void ldsm_x4t(uint32_t* r, uint32_t addr) {
    asm volatile("ldmatrix.sync.aligned.m8n8.x4.trans.shared.b16 {%0,%1,%2,%3}, [%4];"
                 : "=r"(r[0]), "=r"(r[1]), "=r"(r[2]), "=r"(r[3]) : "r"(addr));
}
__device__ __forceinline__ void mma16816(float* c, const uint32_t* a, uint32_t b0, uint32_t b1) {
    asm volatile("mma.sync.aligned.m16n8k16.row.col.f32.f16.f16.f32 "
                 "{%0,%1,%2,%3}, {%4,%5,%6,%7}, {%8,%9}, {%0,%1,%2,%3};"
                 : "+f"(c[0]), "+f"(c[1]), "+f"(c[2]), "+f"(c[3])
                 : "r"(a[0]), "r"(a[1]), "r"(a[2]), "r"(a[3]), "r"(b0), "r"(b1));
}

// ============================================================================
// Pure-fp16 GEMM (R12 config — best measured): tile 128x128, BK=64,
// 8 warps (warp tile 64x32), 3-stage ring, 2 CTA/SM.
// Stage: A 128x144B (18432) + B 64x272B (17408) = 35840; x3 = 107520 B smem.
// ============================================================================
#define A64_PITCH 144
#define A64_BYTES (128 * A64_PITCH)     // 18432
#define B64_BYTES (64 * 272)            // 17408
#define STAGE64 (A64_BYTES + B64_BYTES) // 35840
#define SMEM64 (3 * STAGE64)            // 107520

__global__ __launch_bounds__(256, 2)
void mma_gemm_bk64(const __half* __restrict__ Ah, const __half* __restrict__ Bh,
                   const float* __restrict__ bias, __half* __restrict__ Cout,
                   int M, int N, int K, int doRelu)
{
    extern __shared__ __half smem[];
    const int tid  = threadIdx.x;
    const int lane = tid & 31;
    const int wid  = tid >> 5;
    const int bm = blockIdx.y * 128;
    const int bn = blockIdx.x * 128;
    const int warp_m = (wid & 1) * 64;
    const int warp_n = (wid >> 1) * 32;

    uint32_t su = (uint32_t)__cvta_generic_to_shared(smem);

    float C[4][4][4];
#pragma unroll
    for (int mt = 0; mt < 4; mt++)
#pragma unroll
        for (int nt = 0; nt < 4; nt++)
#pragma unroll
            for (int q = 0; q < 4; q++) C[mt][nt][q] = 0.f;

    const int nk = K / 64;

    auto load_tile = [&](int kt, int st) {
        const int k0 = kt * 64;
        const uint32_t base = su + (uint32_t)st * STAGE64;
#pragma unroll
        for (int t = 0; t < 4; t++) {
            int cid = tid + t * 256;
            int rr  = cid >> 3;
            int cc  = cid & 7;
            int gr  = bm + rr;
            int ok  = (gr < M) ? 16 : 0;
            const __half* src = Ah + (size_t)(ok ? gr : 0) * K + k0 + cc * 8;
            cp16(base + (uint32_t)(rr * A64_PITCH + cc * 16), src, ok);
        }
#pragma unroll
        for (int t = 0; t < 4; t++) {
            int cid = tid + t * 256;
            int rr  = cid >> 4;
            int cc  = cid & 15;
            const __half* src = Bh + (size_t)(k0 + rr) * N + bn + cc * 8;
            cp16(base + A64_BYTES + (uint32_t)(rr * 272 + cc * 16), src, 16);
        }
    };

    load_tile(0, 0);
    asm volatile("cp.async.commit_group;\n" ::: "memory");
    if (nk > 1) load_tile(1, 1);
    asm volatile("cp.async.commit_group;\n" ::: "memory");

    for (int i = 0; i < nk; i++) {
        const int st = i % 3;
        asm volatile("cp.async.wait_group 1;\n" ::: "memory");
        __syncthreads();
        if (i + 2 < nk) load_tile(i + 2, (i + 2) % 3);
        asm volatile("cp.async.commit_group;\n" ::: "memory");

        const uint32_t aS = su + (uint32_t)st * STAGE64;
        const uint32_t bS = aS + A64_BYTES;

        const int arow = lane & 15;
        const int acol = (lane >> 4) * 8;
        const int bk  = ((lane >> 3) & 1) * 8 + (lane & 7);
        const int bn8 = (lane >> 4) * 8;

#pragma unroll
        for (int ks = 0; ks < 64; ks += 16) {
            uint32_t bh[2][4];
#pragma unroll
            for (int ntp = 0; ntp < 2; ntp++) {
                uint32_t boff = (uint32_t)((ks + bk) * 272 + (warp_n + ntp * 16 + bn8) * 2);
                ldsm_x4t(bh[ntp], bS + boff);
            }
            uint32_t ah[4][4];
#pragma unroll
            for (int mt = 0; mt < 4; mt++) {
                uint32_t off = (uint32_t)((warp_m + mt * 16 + arow) * A64_PITCH + (ks + acol) * 2);
                ldsm_x4(ah[mt], aS + off);
            }
#pragma unroll
            for (int mt = 0; mt < 4; mt++)
#pragma unroll
                for (int nt = 0; nt < 4; nt++)
                    mma16816(C[mt][nt], ah[mt],
                             bh[nt >> 1][(nt & 1) * 2], bh[nt >> 1][(nt & 1) * 2 + 1]);
        }
    }

    __syncthreads();

#pragma unroll
    for (int mt = 0; mt < 4; mt++) {
#pragma unroll
        for (int nt = 0; nt < 4; nt++) {
            int r0  = bm + warp_m + mt * 16 + (lane >> 2);
            int col = bn + warp_n + nt * 8 + (lane & 3) * 2;
            float b0 = bias[col], b1 = bias[col + 1];
            float v0 = C[mt][nt][0] + b0;
            float v1 = C[mt][nt][1] + b1;
            float v2 = C[mt][nt][2] + b0;
            float v3 = C[mt][nt][3] + b1;
            if (doRelu) {
                v0 = fmaxf(v0, 0.f); v1 = fmaxf(v1, 0.f);
                v2 = fmaxf(v2, 0.f); v3 = fmaxf(v3, 0.f);
            }
            if (r0 < M) {
                __half2 p; p.x = __float2half(v0); p.y = __float2half(v1);
                *reinterpret_cast<__half2*>(&Cout[(size_t)r0 * N + col]) = p;
            }
            if (r0 + 8 < M) {
                __half2 p; p.x = __float2half(v2); p.y = __float2half(v3);
                *reinterpret_cast<__half2*>(&Cout[(size_t)(r0 + 8) * N + col]) = p;
            }
        }
    }
}

// ---------------- small kernels --------------------------------------------

// single launch converting both k2 and k3 fp32 -> fp16 (grid-stride)
__global__ void convert_both_kernel(const float* __restrict__ k2_w, const float* __restrict__ k3_w)
{
    const int n2 = (WK / 2) * WK;
    const int n3 = WK * WN * WN;
    for (int i = blockIdx.x * blockDim.x + threadIdx.x; i < n2 + n3; i += gridDim.x * blockDim.x) {
        if (i < n2) g_k2[i] = __float2half(k2_w[i]);
        else        g_k3[i - n2] = __float2half(k3_w[i - n2]);
    }
}

// h1 = relu(ea @ k1_w + k1_b), fp16. 256 threads = 2 edges per block.
__global__ __launch_bounds__(256)
void edge_fc1_kernel(const float* __restrict__ ea, const float* __restrict__ w,
                     const float* __restrict__ b, int E)
{
    int sub = threadIdx.x >> 7;
    int tid = threadIdx.x & 127;
    int e = blockIdx.x * 2 + sub;
    if (e >= E) return;
    __shared__ float a[2][IN_W];
    if (tid < IN_W) a[sub][tid] = ea[(size_t)e * IN_W + tid];
    __syncthreads();
    float acc = b[tid];
#pragma unroll
    for (int i = 0; i < IN_W; i++) acc = fmaf(a[sub][i], w[i * (WK / 2) + tid], acc);
    acc = fmaxf(acc, 0.f);
    g_h1[(size_t)e * (WK / 2) + tid] = __float2half(acc);
}

__global__ void deg_kernel(const int* __restrict__ dst, int E)
{
    int e = blockIdx.x * blockDim.x + threadIdx.x;
    if (e < E) atomicAdd(&g_deg[dst[e]], 1.f);
}

__global__ __launch_bounds__(256)
void fc1_kernel(const float* __restrict__ x, const float* __restrict__ w,
                const float* __restrict__ b, int N)
{
    int warp = threadIdx.x >> 5, lane = threadIdx.x & 31;
    int n = blockIdx.x * 8 + warp;
    if (n >= N) return;
    float xv = (lane < IN_W) ? x[(size_t)n * IN_W + lane] : 0.f;
    float acc = b[lane];
#pragma unroll
    for (int i = 0; i < IN_W; i++) {
        float xi = __shfl_sync(0xffffffffu, xv, i);
        acc = fmaf(xi, w[i * WN + lane], acc);
    }
    g_h[(size_t)n * WN + lane] = acc;
}

// per-edge matvec msg = h[src] @ w_e (fp16), scattered to aggr[dst].
// rev flips traversal order (serpentine across depths -> L2 reuse of w_e tail).
__global__ __launch_bounds__(256)
void msg_scatter_kernel(const int* __restrict__ src, const int* __restrict__ dst, int E, int rev)
{
    int warp = threadIdx.x >> 5, lane = threadIdx.x & 31;
    int idx = blockIdx.x * 8 + warp;
    if (idx >= E) return;
    int e = rev ? (E - 1 - idx) : idx;
    int s = src[e], d = dst[e];
    float hv = g_h[(size_t)s * WN + lane];
    const uint4* w4 = reinterpret_cast<const uint4*>(&g_we[(size_t)e * WN * WN]);
    uint4 q0 = w4[lane];
    uint4 q1 = w4[lane + 32];
    uint4 q2 = w4[lane + 64];
    uint4 q3 = w4[lane + 96];
    const int rbase = lane >> 2;
    float acc[8];
#pragma unroll
    for (int j = 0; j < 8; j++) acc[j] = 0.f;

    auto accum = [&](const uint4& q, int k) {
        float hk = __shfl_sync(0xffffffffu, hv, rbase + 8 * k);
        const __half2* hp = reinterpret_cast<const __half2*>(&q);
#pragma unroll
        for (int p = 0; p < 4; p++) {
            float2 wf = __half22float2(hp[p]);
            acc[2 * p]     = fmaf(hk, wf.x, acc[2 * p]);
            acc[2 * p + 1] = fmaf(hk, wf.y, acc[2 * p + 1]);
        }
    };
    accum(q0, 0); accum(q1, 1); accum(q2, 2); accum(q3, 3);

#pragma unroll
    for (int m = 4; m <= 16; m <<= 1)
#pragma unroll
        for (int j = 0; j < 8; j++)
            acc[j] += __shfl_xor_sync(0xffffffffu, acc[j], m);

    if (rbase < 4) {
        float* p = &g_aggr[(size_t)d * WN + 8 * (lane & 3) + 2 * rbase];
        asm volatile("red.global.add.v2.f32 [%0], {%1, %2};"
                     :: "l"(p), "f"(acc[2 * rbase]), "f"(acc[2 * rbase + 1]) : "memory");
    }
}

// h = [relu]( aggr/denom + h @ root_w + conv_b ); also zeroes aggr for next round
__global__ __launch_bounds__(256)
void combine_kernel(const float* __restrict__ root_w, const float* __restrict__ conv_b,
                    int N, int doRelu)
{
    __shared__ float rw[WN * WN];
    __shared__ float cb[WN];
    int tid = threadIdx.x;
    for (int i = tid; i < WN * WN; i += blockDim.x) rw[i] = root_w[i];
    if (tid < WN) cb[tid] = conv_b[tid];
    __syncthreads();

    int warp = tid >> 5, lane = tid & 31;
    int n = blockIdx.x * 8 + warp;
    if (n >= N) return;
    float hv = g_h[(size_t)n * WN + lane];
    float denom = fmaxf(g_deg[n], 1.f);
    float acc = g_aggr[(size_t)n * WN + lane] / denom + cb[lane];
    g_aggr[(size_t)n * WN + lane] = 0.f;
#pragma unroll
    for (int i = 0; i < WN; i++) {
        float hi = __shfl_sync(0xffffffffu, hv, i);
        acc = fmaf(hi, rw[i * WN + lane], acc);
    }
    if (doRelu) acc = fmaxf(acc, 0.f);
    g_h[(size_t)n * WN + lane] = acc;
}

__global__ __launch_bounds__(128)
void head_kernel(const float* __restrict__ fc2_w, const float* __restrict__ fc2_b,
                 const float* __restrict__ fc3_w, const float* __restrict__ fc3_b,
                 float* __restrict__ out)
{
    int n = blockIdx.x, tid = threadIdx.x;
    __shared__ float sh[WN];
    __shared__ float red[4];
    if (tid < WN) sh[tid] = g_h[(size_t)n * WN + tid];
    __syncthreads();
    float a = fc2_b[tid];
#pragma unroll
    for (int i = 0; i < WN; i++) a = fmaf(sh[i], fc2_w[i * 128 + tid], a);
    a = fmaxf(a, 0.f) * fc3_w[tid];
#pragma unroll
    for (int o = 16; o; o >>= 1) a += __shfl_xor_sync(0xffffffffu, a, o);
    if ((tid & 31) == 0) red[tid >> 5] = a;
    __syncthreads();
    if (tid == 0) out[n] = red[0] + red[1] + red[2] + red[3] + fc3_b[0];
}

// ---------------- launch ----------------------------------------------------
extern "C" void kernel_launch(void* const* d_in, const int* in_sizes, int n_in,
                              void* d_out, int out_size)
{
    const float* x      = (const float*)d_in[0];
    const int*   ei     = (const int*)  d_in[1];
    const float* ea     = (const float*)d_in[2];
    const float* fc1_w  = (const float*)d_in[3];
    const float* fc1_b  = (const float*)d_in[4];
    const float* k1_w   = (const float*)d_in[5];
    const float* k1_b   = (const float*)d_in[6];
    const float* k2_w   = (const float*)d_in[7];
    const float* k2_b   = (const float*)d_in[8];
    const float* k3_w   = (const float*)d_in[9];
    const float* k3_b   = (const float*)d_in[10];
    const float* root_w = (const float*)d_in[11];
    const float* conv_b = (const float*)d_in[12];
    const float* fc2_w  = (const float*)d_in[13];
    const float* fc2_b  = (const float*)d_in[14];
    const float* fc3_w  = (const float*)d_in[15];
    const float* fc3_b  = (const float*)d_in[16];
    float* out = (float*)d_out;

    const int N = in_sizes[0] / IN_W;
    const int E = in_sizes[1] / 2;
    const int* src = ei;
    const int* dst = ei + E;

    float *aggr, *deg;
    __half *we, *h1, *h2, *k2, *k3;
    cudaGetSymbolAddress((void**)&we,   g_we);
    cudaGetSymbolAddress((void**)&aggr, g_aggr);
    cudaGetSymbolAddress((void**)&deg,  g_deg);
    cudaGetSymbolAddress((void**)&h1,   g_h1);
    cudaGetSymbolAddress((void**)&h2,   g_h2);
    cudaGetSymbolAddress((void**)&k2,   g_k2);
    cudaGetSymbolAddress((void**)&k3,   g_k3);

    static bool attr_done = false;
    if (!attr_done) {
        cudaFuncSetAttribute(mma_gemm_bk64, cudaFuncAttributeMaxDynamicSharedMemorySize, SMEM64);
        attr_done = true;
    }

    // launch order: GEMM3 at my index 3 (observed ncu -s 5 window)
    edge_fc1_kernel<<<(E + 1) / 2, 256>>>(ea, k1_w, k1_b, E);                              // 0
    convert_both_kernel<<<256, 256>>>(k2_w, k3_w);                                         // 1
    // GEMM2 (pure fp16, BK64): h2 = relu(h1 @ k2 + b2).  M=E, N=256, K=128
    {
        dim3 grid(WK / 128, (E + 127) / 128);
        mma_gemm_bk64<<<grid, 256, SMEM64>>>(h1, k2, k2_b, h2, E, WK, WK / 2, 1);          // 2
    }
    // GEMM3 (pure fp16, BK64): w_e = h2 @ k3 + b3.  M=E, N=1024, K=256
    {
        dim3 grid(WN * WN / 128, (E + 127) / 128);
        mma_gemm_bk64<<<grid, 256, SMEM64>>>(h2, k3, k3_b, we, E, WN * WN, WK, 0);         // 3
    }
    fc1_kernel<<<(N + 7) / 8, 256>>>(x, fc1_w, fc1_b, N);                                  // 4

    // in-degree + one-time aggr clear
    cudaMemsetAsync(deg, 0, (size_t)N * sizeof(float));
    cudaMemsetAsync(aggr, 0, (size_t)N * WN * sizeof(float));
    deg_kernel<<<(E + 255) / 256, 256>>>(dst, E);

    // message passing — serpentine traversal for cross-depth L2 reuse of w_e
    for (int d = 0; d < DEPTH; d++) {
        msg_scatter_kernel<<<(E + 7) / 8, 256>>>(src, dst, E, d & 1);
        combine_kernel<<<(N + 7) / 8, 256>>>(root_w, conv_b, N, d != DEPTH - 1 ? 1 : 0);
    }

    // head
    head_kernel<<<N, 128>>>(fc2_w, fc2_b, fc3_w, fc3_b, out);
}